// round 4
// baseline (speedup 1.0000x reference)
#include <cuda_runtime.h>

#define S_LEN 16384
#define HL 48
#define HR 24

typedef unsigned long long u64;

__device__ u64   g_xw0[(size_t)S_LEN * 96];       // permuted packed gate pairs
__device__ u64   g_xwb[4][(size_t)S_LEN * 96];
__device__ float g_hb[5][(size_t)S_LEN * HL];
__device__ float g_r0[(size_t)S_LEN * HR];
__device__ int   g_cnt[16];

__device__ __forceinline__ u64 pack2(float x, float y) {
    u64 r; asm("mov.b64 %0, {%1, %2};" : "=l"(r) : "f"(x), "f"(y)); return r;
}
__device__ __forceinline__ void unpack2(u64 v, float &x, float &y) {
    asm("mov.b64 {%0, %1}, %2;" : "=f"(x), "=f"(y) : "l"(v));
}
__device__ __forceinline__ u64 ffma2(u64 a, u64 b, u64 c) {
    u64 d; asm("fma.rn.f32x2 %0, %1, %2, %3;" : "=l"(d) : "l"(a), "l"(b), "l"(c)); return d;
}
__device__ __forceinline__ int ld_acq(const int *p) {
    int v; asm volatile("ld.acquire.gpu.global.b32 %0, [%1];" : "=r"(v) : "l"(p)); return v;
}
__device__ __forceinline__ void st_rel(int *p, int v) {
    asm volatile("st.release.gpu.global.b32 [%0], %1;" :: "l"(p), "r"(v));
}
// a=1: sigmoid; a=2: tanh = 2*sigmoid(2x)-1
__device__ __forceinline__ float actf(float x, float a) {
    return __fdividef(a, 1.f + __expf(-a * x)) - (a - 1.f);
}
// gate-pair permutation: thread p owns rows (rX, rY) of the 192-row gate matrix.
// lanes 0-15 of each warp: (i_m, g_m); lanes 16-31: (f_m, o_m); m = 16*warp + (lane&15)
__device__ __forceinline__ void rowpair(int p, int &rX, int &rY) {
    int w = p >> 5, l = p & 31;
    int m = 16 * w + (l & 15);
    if (l < 16) { rX = m;      rY = 96 + m;  }
    else        { rX = 48 + m; rY = 144 + m; }
}

// ------------------- shared memory overlays (union) -------------------
struct LstmSmem { u64 xw[32][96]; u64 hb[2][48]; };
struct XwSmem   { u64 h[16][48]; };
struct Rnn0Smem { float W[24 * 48]; float b[24]; float hin[32][48]; float xw[16][24]; float hb[2][24]; };
struct Rnn1Smem { float W[24 * 24]; float b[24]; float rin[32][24]; float xw[16][24]; float hb[2][24]; };
#define SMEM_MAX sizeof(LstmSmem)

// ---------------- front: fc1 -> relu -> fc2 -> relu -> permuted xw0 ----------------
__global__ void __launch_bounds__(128) front_kernel(
    const float* __restrict__ x,
    const float* __restrict__ fc1W, const float* __restrict__ fc1b,
    const float* __restrict__ fc2W, const float* __restrict__ fc2b,
    const float* __restrict__ Wih0,
    const float* __restrict__ bih0, const float* __restrict__ bhh0)
{
    __shared__ float s1W[120], s1b[20], s2W[400], s2b[20], s0W[3840], s0b[192];
    const int tid = threadIdx.x;
    for (int i = tid; i < 120; i += 128) s1W[i] = fc1W[i];
    for (int i = tid; i < 400; i += 128) s2W[i] = fc2W[i];
    for (int i = tid; i < 3840; i += 128) s0W[i] = Wih0[i];
    for (int i = tid; i < 192; i += 128) s0b[i] = bih0[i] + bhh0[i];
    if (tid < 20) { s1b[tid] = fc1b[tid]; s2b[tid] = fc2b[tid]; }
    if (blockIdx.x == 0 && tid < 16) g_cnt[tid] = 0;
    __syncthreads();

    const int t = blockIdx.x * 128 + tid;
    float xin[6];
#pragma unroll
    for (int i = 0; i < 6; i++) xin[i] = x[t * 6 + i];
    float h1[20];
#pragma unroll
    for (int j = 0; j < 20; j++) {
        float s = s1b[j];
#pragma unroll
        for (int i = 0; i < 6; i++) s += xin[i] * s1W[j * 6 + i];
        h1[j] = fmaxf(s, 0.f);
    }
    float h2[20];
#pragma unroll
    for (int j = 0; j < 20; j++) {
        float s = s2b[j];
#pragma unroll
        for (int i = 0; i < 20; i++) s += h1[i] * s2W[j * 20 + i];
        h2[j] = fmaxf(s, 0.f);
    }
    for (int p = 0; p < 96; p++) {
        int rX, rY; rowpair(p, rX, rY);
        float sX = s0b[rX], sY = s0b[rY];
#pragma unroll
        for (int k = 0; k < 20; k++) {
            float hv = h2[k];
            sX += hv * s0W[rX * 20 + k];
            sY += hv * s0W[rY * 20 + k];
        }
        g_xw0[(size_t)t * 96 + p] = pack2(sX, sY);
    }
}

// ---------------- LSTM recurrence: 1 barrier/step, shfl gate exchange ----------------
__device__ void lstm_rec(unsigned char* smem_raw,
                         const float* __restrict__ Whh, const u64* __restrict__ xwsrc,
                         const int* upcnt, float* __restrict__ hout, int* mycnt)
{
    LstmSmem* sm = reinterpret_cast<LstmSmem*>(smem_raw);
    const int tid = threadIdx.x;
    u64 w[48];
    float c = 0.f;
    float a2sel = 1.f;
    int m = 0;
    bool isA = false;
    if (tid < 96) {
        int rX, rY; rowpair(tid, rX, rY);
        const float* r0 = Whh + rX * HL;
        const float* r1 = Whh + rY * HL;
#pragma unroll
        for (int k = 0; k < 48; k++) w[k] = pack2(r0[k], r1[k]);
        m = 16 * (tid >> 5) + (tid & 15);
        isA = (tid & 31) < 16;
        a2sel = isA ? 2.f : 1.f;    // A: second gate is g (tanh); B: o (sigmoid)
    }
    if (tid < 48) sm->hb[0][tid] = 0ULL;

    int avail = 0;
    if (tid >= 96) {                     // prime ring rows [0,16)
        int lane = tid - 96;
        if (upcnt) { while (avail < 16) avail = ld_acq(upcnt); }
        for (int r = 0; r < 16; r++) {
            const u64* src = xwsrc + (size_t)r * 96;
            sm->xw[r][lane]      = src[lane];
            sm->xw[r][32 + lane] = src[32 + lane];
            sm->xw[r][64 + lane] = src[64 + lane];
        }
    }
    __syncthreads();

    for (int t = 0; t < S_LEN; t++) {
        if (tid < 96) {
            u64 a0 = sm->xw[t & 31][tid], a1 = 0, a2 = 0, a3 = 0;
            const ulonglong2* hd2 = (const ulonglong2*)sm->hb[t & 1];
#pragma unroll
            for (int k = 0; k < 12; k++) {
                ulonglong2 h0 = hd2[2 * k], h1 = hd2[2 * k + 1];
                a0 = ffma2(h0.x, w[4 * k], a0);
                a1 = ffma2(h0.y, w[4 * k + 1], a1);
                a2 = ffma2(h1.x, w[4 * k + 2], a2);
                a3 = ffma2(h1.y, w[4 * k + 3], a3);
            }
            float x0, y0, x1, y1, x2, y2, x3, y3;
            unpack2(a0, x0, y0); unpack2(a1, x1, y1);
            unpack2(a2, x2, y2); unpack2(a3, x3, y3);
            float gx = (x0 + x1) + (x2 + x3);
            float gy = (y0 + y1) + (y2 + y3);
            float ax = actf(gx, 1.f);        // A: i        B: f
            float ay = actf(gy, a2sel);      // A: g(tanh)  B: o
            float fv = __shfl_down_sync(0xffffffffu, ax, 16);
            float ov = __shfl_down_sync(0xffffffffu, ay, 16);
            if (isA) {
                c = fv * c + ax * ay;
                float h = ov * actf(c, 2.f);
                sm->hb[(t + 1) & 1][m] = pack2(h, h);
                hout[(size_t)t * HL + m] = h;
            }
        } else {
            int ph = t & 7;
            if (ph == 0) {
                int lane = tid - 96;
                int B = t;
                int need = B + 24; if (need > S_LEN) need = S_LEN;
                if (upcnt && avail < need) { do { avail = ld_acq(upcnt); } while (avail < need); }
#pragma unroll
                for (int r = 0; r < 8; r++) {
                    int row = B + 16 + r;
                    if (row < S_LEN) {
                        const u64* src = xwsrc + (size_t)row * 96;
                        sm->xw[row & 31][lane]      = src[lane];
                        sm->xw[row & 31][32 + lane] = src[32 + lane];
                        sm->xw[row & 31][64 + lane] = src[64 + lane];
                    }
                }
            }
        }
        __syncthreads();
        if (tid == 0) st_rel(mycnt, t + 1);
    }
}

// ---------------- feedforward xw stage (LSTM layers 1..4), batch-8 ----------------
__device__ void xw_stage(unsigned char* smem_raw,
                         const float* __restrict__ Wih, const float* __restrict__ bih,
                         const float* __restrict__ bhh, const float* __restrict__ hin,
                         const int* upcnt, u64* __restrict__ xwout, int* mycnt)
{
    XwSmem* sm = reinterpret_cast<XwSmem*>(smem_raw);
    const int tid = threadIdx.x;
    u64 w[48], bias = 0ULL;
    if (tid < 96) {
        int rX, rY; rowpair(tid, rX, rY);
        const float* r0 = Wih + rX * HL;
        const float* r1 = Wih + rY * HL;
#pragma unroll
        for (int k = 0; k < 48; k++) w[k] = pack2(r0[k], r1[k]);
        bias = pack2(bih[rX] + bhh[rX], bih[rY] + bhh[rY]);
    }
    int avail = 0;
    if (tid >= 96) {                     // prime rows [0,8)
        int lane = tid - 96;
        while (avail < 8) avail = ld_acq(upcnt);
        for (int i = lane; i < 8 * 48; i += 32) {
            int r = i / 48, col = i % 48;
            float v = hin[(size_t)r * HL + col];
            sm->h[r][col] = pack2(v, v);
        }
    }
    __syncthreads();
    for (int B = 0; B < S_LEN; B += 8) {
        if (tid < 96) {
#pragma unroll
            for (int s = 0; s < 8; s++) {
                int t = B + s;
                const ulonglong2* hs = (const ulonglong2*)sm->h[t & 15];
                u64 a0 = bias, a1 = 0, a2 = 0, a3 = 0;
#pragma unroll
                for (int k = 0; k < 12; k++) {
                    ulonglong2 h0 = hs[2 * k], h1 = hs[2 * k + 1];
                    a0 = ffma2(h0.x, w[4 * k], a0);
                    a1 = ffma2(h0.y, w[4 * k + 1], a1);
                    a2 = ffma2(h1.x, w[4 * k + 2], a2);
                    a3 = ffma2(h1.y, w[4 * k + 3], a3);
                }
                float x0, y0, x1, y1, x2, y2, x3, y3;
                unpack2(a0, x0, y0); unpack2(a1, x1, y1);
                unpack2(a2, x2, y2); unpack2(a3, x3, y3);
                xwout[(size_t)t * 96 + tid] =
                    pack2((x0 + x1) + (x2 + x3), (y0 + y1) + (y2 + y3));
            }
        } else {
            int lane = tid - 96;
            int need = B + 16; if (need > S_LEN) need = S_LEN;
            if (avail < need) { do { avail = ld_acq(upcnt); } while (avail < need); }
            for (int i = lane; i < 8 * 48; i += 32) {
                int r = i / 48, col = i % 48;
                int row = B + 8 + r;
                if (row < S_LEN) {
                    float v = hin[(size_t)row * HL + col];
                    sm->h[row & 15][col] = pack2(v, v);
                }
            }
        }
        __syncthreads();
        if (tid == 0) st_rel(mycnt, B + 8);
    }
}

// ---------------- RNN0: 48 -> 24, batch-8, warp-specialized ----------------
__device__ void rnn0_stage(unsigned char* smem_raw,
                           const float* __restrict__ Wih, const float* __restrict__ Whh,
                           const float* __restrict__ bih, const float* __restrict__ bhh,
                           const float* __restrict__ hin, const int* upcnt,
                           float* __restrict__ rout, int* mycnt)
{
    Rnn0Smem* sm = reinterpret_cast<Rnn0Smem*>(smem_raw);
    const int tid = threadIdx.x;
    const int wid = tid >> 5, lane = tid & 31;
    for (int i = tid; i < 24 * 48; i += 128) sm->W[i] = Wih[i];
    if (tid < 24) { sm->b[tid] = bih[tid] + bhh[tid]; sm->hb[0][tid] = 0.f; }
    float wh[24];
    if (wid == 0 && lane < 24) {
#pragma unroll
        for (int k = 0; k < 24; k++) wh[k] = Whh[lane * HR + k];
    }
    int avail = 0;
    if (wid == 3) {                      // prime hin rows [0,16)
        while (avail < 16) avail = ld_acq(upcnt);
        for (int i = lane; i < 16 * 48; i += 32) sm->hin[i / 48][i % 48] = hin[i];
    }
    __syncthreads();
    if (wid == 1 || wid == 2) {          // prime xw steps [0,8)
        int idx = tid - 32;
#pragma unroll
        for (int q = 0; q < 3; q++) {
            int d = idx + 64 * q;
            int s = d / 24, j = d % 24;
            const float* hrow = sm->hin[s];
            const float* wr = &sm->W[j * 48];
            float a0 = sm->b[j], a1 = 0, a2 = 0, a3 = 0;
#pragma unroll
            for (int k = 0; k < 48; k += 4) {
                a0 += hrow[k] * wr[k];         a1 += hrow[k + 1] * wr[k + 1];
                a2 += hrow[k + 2] * wr[k + 2]; a3 += hrow[k + 3] * wr[k + 3];
            }
            sm->xw[s][j] = (a0 + a1) + (a2 + a3);
        }
    }
    __syncthreads();
    for (int B = 0; B < S_LEN; B += 8) {
        if (wid == 0) {
#pragma unroll 1
            for (int s = 0; s < 8; s++) {
                int t = B + s;
                if (lane < 24) {
                    const float* hp = sm->hb[t & 1];
                    float a0 = sm->xw[t & 15][lane], a1 = 0, a2 = 0, a3 = 0;
#pragma unroll
                    for (int k = 0; k < 24; k += 4) {
                        a0 += hp[k] * wh[k];         a1 += hp[k + 1] * wh[k + 1];
                        a2 += hp[k + 2] * wh[k + 2]; a3 += hp[k + 3] * wh[k + 3];
                    }
                    float h = actf((a0 + a1) + (a2 + a3), 2.f);
                    sm->hb[(t + 1) & 1][lane] = h;
                    rout[(size_t)t * HR + lane] = h;
                }
                __syncwarp();
            }
        } else if (wid == 1 || wid == 2) {   // xw for steps [B+8, B+16)
            int idx = tid - 32;
#pragma unroll
            for (int q = 0; q < 3; q++) {
                int d = idx + 64 * q;
                int s = d / 24, j = d % 24;
                int t = B + 8 + s;
                if (t < S_LEN) {
                    const float* hrow = sm->hin[t & 31];
                    const float* wr = &sm->W[j * 48];
                    float a0 = sm->b[j], a1 = 0, a2 = 0, a3 = 0;
#pragma unroll
                    for (int k = 0; k < 48; k += 4) {
                        a0 += hrow[k] * wr[k];         a1 += hrow[k + 1] * wr[k + 1];
                        a2 += hrow[k + 2] * wr[k + 2]; a3 += hrow[k + 3] * wr[k + 3];
                    }
                    sm->xw[t & 15][j] = (a0 + a1) + (a2 + a3);
                }
            }
        } else {                              // loader: rows [B+16, B+24)
            int need = B + 24; if (need > S_LEN) need = S_LEN;
            if (avail < need) { do { avail = ld_acq(upcnt); } while (avail < need); }
            for (int i = lane; i < 8 * 48; i += 32) {
                int r = i / 48, col = i % 48;
                int row = B + 16 + r;
                if (row < S_LEN) sm->hin[row & 31][col] = hin[(size_t)row * HL + col];
            }
        }
        __syncthreads();
        if (tid == 0) st_rel(mycnt, B + 8);
    }
}

// ---------------- RNN1 + relu + fc4 -> out, batch-8 ----------------
__device__ void rnn1_stage(unsigned char* smem_raw,
                           const float* __restrict__ Wih, const float* __restrict__ Whh,
                           const float* __restrict__ bih, const float* __restrict__ bhh,
                           const float* __restrict__ rin, const int* upcnt,
                           const float* __restrict__ fc4W, const float* __restrict__ fc4b,
                           float* __restrict__ out)
{
    Rnn1Smem* sm = reinterpret_cast<Rnn1Smem*>(smem_raw);
    const int tid = threadIdx.x;
    const int wid = tid >> 5, lane = tid & 31;
    for (int i = tid; i < 24 * 24; i += 128) sm->W[i] = Wih[i];
    if (tid < 24) { sm->b[tid] = bih[tid] + bhh[tid]; sm->hb[0][tid] = 0.f; }
    float wh[24], wf[24], bf = 0.f;
    if (wid == 0 && lane < 24) {
#pragma unroll
        for (int k = 0; k < 24; k++) wh[k] = Whh[lane * HR + k];
    }
    if (wid == 0 && (lane == 24 || lane == 25)) {
#pragma unroll
        for (int k = 0; k < 24; k++) wf[k] = fc4W[(lane - 24) * HR + k];
        bf = fc4b[lane - 24];
    }
    int avail = 0;
    if (wid == 3) {                      // prime rin rows [0,16)
        while (avail < 16) avail = ld_acq(upcnt);
        for (int i = lane; i < 16 * 24; i += 32) sm->rin[i / 24][i % 24] = rin[i];
    }
    __syncthreads();
    if (wid == 1 || wid == 2) {          // prime xw steps [0,8)
        int idx = tid - 32;
#pragma unroll
        for (int q = 0; q < 3; q++) {
            int d = idx + 64 * q;
            int s = d / 24, j = d % 24;
            const float* hrow = sm->rin[s];
            const float* wr = &sm->W[j * 24];
            float a0 = sm->b[j], a1 = 0, a2 = 0, a3 = 0;
#pragma unroll
            for (int k = 0; k < 24; k += 4) {
                a0 += hrow[k] * wr[k];         a1 += hrow[k + 1] * wr[k + 1];
                a2 += hrow[k + 2] * wr[k + 2]; a3 += hrow[k + 3] * wr[k + 3];
            }
            sm->xw[s][j] = (a0 + a1) + (a2 + a3);
        }
    }
    __syncthreads();
    for (int B = 0; B < S_LEN; B += 8) {
        if (wid == 0) {
#pragma unroll 1
            for (int s = 0; s < 8; s++) {
                int t = B + s;
                if (lane < 24) {
                    const float* hp = sm->hb[t & 1];
                    float a0 = sm->xw[t & 15][lane], a1 = 0, a2 = 0, a3 = 0;
#pragma unroll
                    for (int k = 0; k < 24; k += 4) {
                        a0 += hp[k] * wh[k];         a1 += hp[k + 1] * wh[k + 1];
                        a2 += hp[k + 2] * wh[k + 2]; a3 += hp[k + 3] * wh[k + 3];
                    }
                    float h = actf((a0 + a1) + (a2 + a3), 2.f);
                    sm->hb[(t + 1) & 1][lane] = h;
                }
                __syncwarp();
                if (lane == 24 || lane == 25) {
                    const float* hc = sm->hb[(t + 1) & 1];
                    float a0 = bf, a1 = 0, a2 = 0, a3 = 0;
#pragma unroll
                    for (int k = 0; k < 24; k += 4) {
                        a0 += fmaxf(hc[k], 0.f) * wf[k];
                        a1 += fmaxf(hc[k + 1], 0.f) * wf[k + 1];
                        a2 += fmaxf(hc[k + 2], 0.f) * wf[k + 2];
                        a3 += fmaxf(hc[k + 3], 0.f) * wf[k + 3];
                    }
                    out[(size_t)t * 2 + (lane - 24)] = (a0 + a1) + (a2 + a3);
                }
                __syncwarp();
            }
        } else if (wid == 1 || wid == 2) {   // xw for steps [B+8, B+16)
            int idx = tid - 32;
#pragma unroll
            for (int q = 0; q < 3; q++) {
                int d = idx + 64 * q;
                int s = d / 24, j = d % 24;
                int t = B + 8 + s;
                if (t < S_LEN) {
                    const float* hrow = sm->rin[t & 31];
                    const float* wr = &sm->W[j * 24];
                    float a0 = sm->b[j], a1 = 0, a2 = 0, a3 = 0;
#pragma unroll
                    for (int k = 0; k < 24; k += 4) {
                        a0 += hrow[k] * wr[k];         a1 += hrow[k + 1] * wr[k + 1];
                        a2 += hrow[k + 2] * wr[k + 2]; a3 += hrow[k + 3] * wr[k + 3];
                    }
                    sm->xw[t & 15][j] = (a0 + a1) + (a2 + a3);
                }
            }
        } else {                              // loader: rows [B+16, B+24)
            int need = B + 24; if (need > S_LEN) need = S_LEN;
            if (avail < need) { do { avail = ld_acq(upcnt); } while (avail < need); }
            for (int i = lane; i < 8 * 24; i += 32) {
                int r = i / 24, col = i % 24;
                int row = B + 16 + r;
                if (row < S_LEN) sm->rin[row & 31][col] = rin[(size_t)row * HR + col];
            }
        }
        __syncthreads();
    }
}

// ---------------- pipeline dispatcher ----------------
__global__ void __launch_bounds__(128, 1) pipe_kernel(
    const float* lstm0_Whh,
    const float* lstmr_Wih, const float* lstmr_Whh,
    const float* lstmr_bih, const float* lstmr_bhh,
    const float* rnn0_Wih, const float* rnn0_Whh,
    const float* rnn0_bih, const float* rnn0_bhh,
    const float* rnn1_Wih, const float* rnn1_Whh,
    const float* rnn1_bih, const float* rnn1_bhh,
    const float* fc4W, const float* fc4b,
    float* out)
{
    __shared__ __align__(16) unsigned char smem[SMEM_MAX];
    const int b = blockIdx.x;
    if (b == 0) {
        lstm_rec(smem, lstm0_Whh, g_xw0, 0, g_hb[0], &g_cnt[0]);
    } else if (b <= 8) {
        int l = (b - 1) / 2;
        if ((b & 1) == 1) {
            xw_stage(smem,
                     lstmr_Wih + (size_t)l * 192 * HL,
                     lstmr_bih + (size_t)l * 192,
                     lstmr_bhh + (size_t)l * 192,
                     g_hb[l], &g_cnt[2 * l], g_xwb[l], &g_cnt[2 * l + 1]);
        } else {
            lstm_rec(smem,
                     lstmr_Whh + (size_t)l * 192 * HL,
                     g_xwb[l], &g_cnt[2 * l + 1], g_hb[l + 1], &g_cnt[2 * l + 2]);
        }
    } else if (b == 9) {
        rnn0_stage(smem, rnn0_Wih, rnn0_Whh, rnn0_bih, rnn0_bhh,
                   g_hb[4], &g_cnt[8], g_r0, &g_cnt[9]);
    } else {
        rnn1_stage(smem, rnn1_Wih, rnn1_Whh, rnn1_bih, rnn1_bhh,
                   g_r0, &g_cnt[9], fc4W, fc4b, out);
    }
}

extern "C" void kernel_launch(void* const* d_in, const int* in_sizes, int n_in,
                              void* d_out, int out_size) {
    const float* x         = (const float*)d_in[0];
    const float* fc1_W     = (const float*)d_in[1];
    const float* fc1_b     = (const float*)d_in[2];
    const float* fc2_W     = (const float*)d_in[3];
    const float* fc2_b     = (const float*)d_in[4];
    const float* lstm0_Wih = (const float*)d_in[5];
    const float* lstm0_Whh = (const float*)d_in[6];
    const float* lstm0_bih = (const float*)d_in[7];
    const float* lstm0_bhh = (const float*)d_in[8];
    const float* lstmr_Wih = (const float*)d_in[9];
    const float* lstmr_Whh = (const float*)d_in[10];
    const float* lstmr_bih = (const float*)d_in[11];
    const float* lstmr_bhh = (const float*)d_in[12];
    const float* rnn0_Wih  = (const float*)d_in[13];
    const float* rnn0_Whh  = (const float*)d_in[14];
    const float* rnn0_bih  = (const float*)d_in[15];
    const float* rnn0_bhh  = (const float*)d_in[16];
    const float* rnn1_Wih  = (const float*)d_in[17];
    const float* rnn1_Whh  = (const float*)d_in[18];
    const float* rnn1_bih  = (const float*)d_in[19];
    const float* rnn1_bhh  = (const float*)d_in[20];
    const float* fc4_W     = (const float*)d_in[21];
    const float* fc4_b     = (const float*)d_in[22];
    float* out = (float*)d_out;

    front_kernel<<<S_LEN / 128, 128>>>(x, fc1_W, fc1_b, fc2_W, fc2_b,
                                       lstm0_Wih, lstm0_bih, lstm0_bhh);
    pipe_kernel<<<11, 128>>>(lstm0_Whh,
                             lstmr_Wih, lstmr_Whh, lstmr_bih, lstmr_bhh,
                             rnn0_Wih, rnn0_Whh, rnn0_bih, rnn0_bhh,
                             rnn1_Wih, rnn1_Whh, rnn1_bih, rnn1_bhh,
                             fc4_W, fc4_b, out);
}

// round 5
// speedup vs baseline: 1.9903x; 1.9903x over previous
#include <cuda_runtime.h>

#define S_LEN 16384
#define HL 48
#define HR 24

typedef unsigned long long u64;

__device__ u64   g_xw0[(size_t)S_LEN * 96];       // permuted packed gate pairs
__device__ u64   g_xwb[4][(size_t)S_LEN * 96];
__device__ float g_hb[5][(size_t)S_LEN * HL];
__device__ float g_r0[(size_t)S_LEN * HR];
__device__ int   g_cnt[16];

#define BARS(id, cnt) asm volatile("bar.sync %0, %1;" :: "r"(id), "r"(cnt) : "memory")

__device__ __forceinline__ u64 pack2(float x, float y) {
    u64 r; asm("mov.b64 %0, {%1, %2};" : "=l"(r) : "f"(x), "f"(y)); return r;
}
__device__ __forceinline__ void unpack2(u64 v, float &x, float &y) {
    asm("mov.b64 {%0, %1}, %2;" : "=f"(x), "=f"(y) : "l"(v));
}
__device__ __forceinline__ u64 ffma2(u64 a, u64 b, u64 c) {
    u64 d; asm("fma.rn.f32x2 %0, %1, %2, %3;" : "=l"(d) : "l"(a), "l"(b), "l"(c)); return d;
}
__device__ __forceinline__ int ld_acq(const int *p) {
    int v; asm volatile("ld.acquire.gpu.global.b32 %0, [%1];" : "=r"(v) : "l"(p)); return v;
}
__device__ __forceinline__ void st_rel(int *p, int v) {
    asm volatile("st.release.gpu.global.b32 [%0], %1;" :: "l"(p), "r"(v));
}
__device__ __forceinline__ float tanhap(float x) {
    float y; asm("tanh.approx.f32 %0, %1;" : "=f"(y) : "f"(x)); return y;
}
__device__ __forceinline__ float sigap(float x) {
    return 0.5f * tanhap(0.5f * x) + 0.5f;
}
// gate-pair permutation: thread p owns rows (rX, rY) of the 192-row gate matrix.
// lanes 0-15 of each warp: (i_m, g_m); lanes 16-31: (f_m, o_m); m = 16*warp + (lane&15)
__device__ __forceinline__ void rowpair(int p, int &rX, int &rY) {
    int w = p >> 5, l = p & 31;
    int m = 16 * w + (l & 15);
    if (l < 16) { rX = m;      rY = 96 + m;  }
    else        { rX = 48 + m; rY = 144 + m; }
}

// ------------------- shared memory overlays -------------------
struct LstmSmem { u64 xw[16][96]; u64 hb[2][48]; };
struct XwSmem   { u64 h[16][48]; };
struct Rnn0Smem { float W[24 * 48]; float b[24]; float hin[16][48]; float xw[16][24]; float hb[2][24]; };
struct Rnn1Smem { float W[24 * 24]; float b[24]; float rin[16][24]; float xw[16][24]; float hb[2][24]; };
#define SMEM_MAX sizeof(LstmSmem)

// ---------------- front: fc1 -> relu -> fc2 -> relu -> permuted xw0 ----------------
__global__ void __launch_bounds__(128) front_kernel(
    const float* __restrict__ x,
    const float* __restrict__ fc1W, const float* __restrict__ fc1b,
    const float* __restrict__ fc2W, const float* __restrict__ fc2b,
    const float* __restrict__ Wih0,
    const float* __restrict__ bih0, const float* __restrict__ bhh0)
{
    __shared__ float s1W[120], s1b[20], s2W[400], s2b[20], s0W[3840], s0b[192];
    const int tid = threadIdx.x;
    for (int i = tid; i < 120; i += 128) s1W[i] = fc1W[i];
    for (int i = tid; i < 400; i += 128) s2W[i] = fc2W[i];
    for (int i = tid; i < 3840; i += 128) s0W[i] = Wih0[i];
    for (int i = tid; i < 192; i += 128) s0b[i] = bih0[i] + bhh0[i];
    if (tid < 20) { s1b[tid] = fc1b[tid]; s2b[tid] = fc2b[tid]; }
    if (blockIdx.x == 0 && tid < 16) g_cnt[tid] = 0;
    __syncthreads();

    const int t = blockIdx.x * 128 + tid;
    float xin[6];
#pragma unroll
    for (int i = 0; i < 6; i++) xin[i] = x[t * 6 + i];
    float h1[20];
#pragma unroll
    for (int j = 0; j < 20; j++) {
        float s = s1b[j];
#pragma unroll
        for (int i = 0; i < 6; i++) s += xin[i] * s1W[j * 6 + i];
        h1[j] = fmaxf(s, 0.f);
    }
    float h2[20];
#pragma unroll
    for (int j = 0; j < 20; j++) {
        float s = s2b[j];
#pragma unroll
        for (int i = 0; i < 20; i++) s += h1[i] * s2W[j * 20 + i];
        h2[j] = fmaxf(s, 0.f);
    }
    for (int p = 0; p < 96; p++) {
        int rX, rY; rowpair(p, rX, rY);
        float sX = s0b[rX], sY = s0b[rY];
#pragma unroll
        for (int k = 0; k < 20; k++) {
            float hv = h2[k];
            sX += hv * s0W[rX * 20 + k];
            sY += hv * s0W[rY * 20 + k];
        }
        g_xw0[(size_t)t * 96 + p] = pack2(sX, sY);
    }
}

// ---------------- LSTM recurrence: decoupled loader, shfl gate exchange ----------------
__device__ void lstm_rec(unsigned char* smem_raw,
                         const float* __restrict__ Whh, const u64* __restrict__ xwsrc,
                         const int* upcnt, float* __restrict__ hout, int* mycnt)
{
    LstmSmem* sm = reinterpret_cast<LstmSmem*>(smem_raw);
    const int tid = threadIdx.x;

    if (tid < 96) {
        u64 w[48];
        int rX, rY; rowpair(tid, rX, rY);
        const float* r0 = Whh + rX * HL;
        const float* r1 = Whh + rY * HL;
#pragma unroll
        for (int k = 0; k < 48; k++) w[k] = pack2(r0[k], r1[k]);
        const int m = 16 * (tid >> 5) + (tid & 15);
        const bool isA = (tid & 31) < 16;
        float c = 0.f;
        if (tid < 48) sm->hb[0][tid] = 0ULL;
        __syncthreads();

        for (int t = 0; t < S_LEN; t++) {
            u64 a0 = sm->xw[t & 15][tid], a1 = 0, a2 = 0, a3 = 0;
            const ulonglong2* hd2 = (const ulonglong2*)sm->hb[t & 1];
#pragma unroll
            for (int k = 0; k < 12; k++) {
                ulonglong2 h0 = hd2[2 * k], h1 = hd2[2 * k + 1];
                a0 = ffma2(h0.x, w[4 * k], a0);
                a1 = ffma2(h0.y, w[4 * k + 1], a1);
                a2 = ffma2(h1.x, w[4 * k + 2], a2);
                a3 = ffma2(h1.y, w[4 * k + 3], a3);
            }
            float x0, y0, x1, y1, x2, y2, x3, y3;
            unpack2(a0, x0, y0); unpack2(a1, x1, y1);
            unpack2(a2, x2, y2); unpack2(a3, x3, y3);
            float gx = (x0 + x1) + (x2 + x3);
            float gy = (y0 + y1) + (y2 + y3);
            float ax = sigap(gx);                       // A: i   B: f
            float pre = isA ? gy : 0.5f * gy;
            float th = tanhap(pre);
            float ay = isA ? th : (0.5f * th + 0.5f);   // A: g(tanh)  B: o(sig)
            float fv = __shfl_down_sync(0xffffffffu, ax, 16);
            float ov = __shfl_down_sync(0xffffffffu, ay, 16);
            if (isA) {
                c = fv * c + ax * ay;
                float h = ov * tanhap(c);
                sm->hb[(t + 1) & 1][m] = pack2(h, h);
                hout[(size_t)t * HL + m] = h;
            }
            BARS(2, 96);
            if ((t & 3) == 3) BARS(1, 128);
        }
    } else {
        const int lane = tid - 96;
        u64 rg[2][3];
        int avail = 0;
        if (upcnt) { while (avail < 14) avail = ld_acq(upcnt); }
        for (int r = 0; r < 12; r++) {
            const u64* src = xwsrc + (size_t)r * 96;
            u64* dst = sm->xw[r];
            dst[lane] = src[lane]; dst[32 + lane] = src[32 + lane]; dst[64 + lane] = src[64 + lane];
        }
        {
            const u64* s12 = xwsrc + (size_t)12 * 96;
            const u64* s13 = xwsrc + (size_t)13 * 96;
            rg[0][0] = s12[lane]; rg[0][1] = s12[32 + lane]; rg[0][2] = s12[64 + lane];
            rg[1][0] = s13[lane]; rg[1][1] = s13[32 + lane]; rg[1][2] = s13[64 + lane];
        }
        __syncthreads();

        for (int t = 0; t < S_LEN; t++) {
            int r_sts = t + 12;
            if (r_sts < S_LEN) {
                u64* dst = sm->xw[r_sts & 15];
                dst[lane] = rg[t & 1][0]; dst[32 + lane] = rg[t & 1][1]; dst[64 + lane] = rg[t & 1][2];
            }
            int r_ldg = t + 14;
            if (r_ldg < S_LEN) {
                if (upcnt && avail <= r_ldg) { do { avail = ld_acq(upcnt); } while (avail <= r_ldg); }
                const u64* src = xwsrc + (size_t)r_ldg * 96;
                rg[t & 1][0] = src[lane]; rg[t & 1][1] = src[32 + lane]; rg[t & 1][2] = src[64 + lane];
            }
            if ((t & 3) == 3) {
                BARS(1, 128);
                if (lane == 0) st_rel(mycnt, t + 1);
            }
        }
    }
}

// ---------------- feedforward xw stage (LSTM layers 1..4) ----------------
__device__ void xw_stage(unsigned char* smem_raw,
                         const float* __restrict__ Wih, const float* __restrict__ bih,
                         const float* __restrict__ bhh, const float* __restrict__ hin,
                         const int* upcnt, u64* __restrict__ xwout, int* mycnt)
{
    XwSmem* sm = reinterpret_cast<XwSmem*>(smem_raw);
    const int tid = threadIdx.x;

    if (tid < 96) {
        u64 w[48], bias;
        int rX, rY; rowpair(tid, rX, rY);
        const float* r0 = Wih + rX * HL;
        const float* r1 = Wih + rY * HL;
#pragma unroll
        for (int k = 0; k < 48; k++) w[k] = pack2(r0[k], r1[k]);
        bias = pack2(bih[rX] + bhh[rX], bih[rY] + bhh[rY]);
        __syncthreads();

        for (int t = 0; t < S_LEN; t++) {
            const ulonglong2* hs = (const ulonglong2*)sm->h[t & 15];
            u64 a0 = bias, a1 = 0, a2 = 0, a3 = 0;
#pragma unroll
            for (int k = 0; k < 12; k++) {
                ulonglong2 h0 = hs[2 * k], h1 = hs[2 * k + 1];
                a0 = ffma2(h0.x, w[4 * k], a0);
                a1 = ffma2(h0.y, w[4 * k + 1], a1);
                a2 = ffma2(h1.x, w[4 * k + 2], a2);
                a3 = ffma2(h1.y, w[4 * k + 3], a3);
            }
            float x0, y0, x1, y1, x2, y2, x3, y3;
            unpack2(a0, x0, y0); unpack2(a1, x1, y1);
            unpack2(a2, x2, y2); unpack2(a3, x3, y3);
            xwout[(size_t)t * 96 + tid] = pack2((x0 + x1) + (x2 + x3), (y0 + y1) + (y2 + y3));
            if ((t & 3) == 3) BARS(1, 128);
        }
    } else {
        const int lane = tid - 96;
        float fg[2][2];
        int avail = 0;
        while (avail < 14) avail = ld_acq(upcnt);
        for (int r = 0; r < 12; r++) {
            const float* src = hin + (size_t)r * HL;
            float v = src[lane]; sm->h[r][lane] = pack2(v, v);
            if (lane < 16) { float v2 = src[32 + lane]; sm->h[r][32 + lane] = pack2(v2, v2); }
        }
        {
            const float* s12 = hin + (size_t)12 * HL;
            const float* s13 = hin + (size_t)13 * HL;
            fg[0][0] = s12[lane]; fg[0][1] = (lane < 16) ? s12[32 + lane] : 0.f;
            fg[1][0] = s13[lane]; fg[1][1] = (lane < 16) ? s13[32 + lane] : 0.f;
        }
        __syncthreads();

        for (int t = 0; t < S_LEN; t++) {
            int r_sts = t + 12;
            if (r_sts < S_LEN) {
                u64* dst = sm->h[r_sts & 15];
                dst[lane] = pack2(fg[t & 1][0], fg[t & 1][0]);
                if (lane < 16) dst[32 + lane] = pack2(fg[t & 1][1], fg[t & 1][1]);
            }
            int r_ldg = t + 14;
            if (r_ldg < S_LEN) {
                if (avail <= r_ldg) { do { avail = ld_acq(upcnt); } while (avail <= r_ldg); }
                const float* src = hin + (size_t)r_ldg * HL;
                fg[t & 1][0] = src[lane];
                if (lane < 16) fg[t & 1][1] = src[32 + lane];
            }
            if ((t & 3) == 3) {
                BARS(1, 128);
                if (lane == 0) st_rel(mycnt, t + 1);
            }
        }
    }
}

// ---------------- RNN0: 48 -> 24 ----------------
__device__ void rnn0_stage(unsigned char* smem_raw,
                           const float* __restrict__ Wih, const float* __restrict__ Whh,
                           const float* __restrict__ bih, const float* __restrict__ bhh,
                           const float* __restrict__ hin, const int* upcnt,
                           float* __restrict__ rout, int* mycnt)
{
    Rnn0Smem* sm = reinterpret_cast<Rnn0Smem*>(smem_raw);
    const int tid = threadIdx.x;
    const int wid = tid >> 5, lane = tid & 31;
    for (int i = tid; i < 24 * 48; i += 128) sm->W[i] = Wih[i];
    if (tid < 24) { sm->b[tid] = bih[tid] + bhh[tid]; sm->hb[0][tid] = 0.f; }

    if (wid == 0) {                      // recurrence warp
        float wh[24];
        if (lane < 24) {
#pragma unroll
            for (int k = 0; k < 24; k++) wh[k] = Whh[lane * HR + k];
        }
        __syncthreads();
        BARS(2, 64);                     // wait xw[0] primed by warp 1
        for (int t = 0; t < S_LEN; t++) {
            if (lane < 24) {
                const float* hp = sm->hb[t & 1];
                float a0 = sm->xw[t & 15][lane], a1 = 0, a2 = 0, a3 = 0;
#pragma unroll
                for (int k = 0; k < 24; k += 4) {
                    a0 += hp[k] * wh[k];         a1 += hp[k + 1] * wh[k + 1];
                    a2 += hp[k + 2] * wh[k + 2]; a3 += hp[k + 3] * wh[k + 3];
                }
                float h = tanhap((a0 + a1) + (a2 + a3));
                sm->hb[(t + 1) & 1][lane] = h;
                rout[(size_t)t * HR + lane] = h;
            }
            BARS(2, 64);
            if ((t & 3) == 3) BARS(1, 96);
        }
    } else if (wid == 1) {               // input-projection warp (one step ahead)
        float wi[48], bsum = 0.f;
        if (lane < 24) {
#pragma unroll
            for (int k = 0; k < 48; k++) wi[k] = Wih[lane * HL + k];
            bsum = bih[lane] + bhh[lane];
        }
        __syncthreads();
        if (lane < 24) {                 // prime xw[0]
            const float* hrow = sm->hin[0];
            float a0 = bsum, a1 = 0, a2 = 0, a3 = 0;
#pragma unroll
            for (int k = 0; k < 48; k += 4) {
                a0 += hrow[k] * wi[k];         a1 += hrow[k + 1] * wi[k + 1];
                a2 += hrow[k + 2] * wi[k + 2]; a3 += hrow[k + 3] * wi[k + 3];
            }
            sm->xw[0][lane] = (a0 + a1) + (a2 + a3);
        }
        BARS(2, 64);
        for (int t = 0; t < S_LEN; t++) {
            int tt = t + 1;
            if (tt < S_LEN && lane < 24) {
                const float* hrow = sm->hin[tt & 15];
                float a0 = bsum, a1 = 0, a2 = 0, a3 = 0;
#pragma unroll
                for (int k = 0; k < 48; k += 4) {
                    a0 += hrow[k] * wi[k];         a1 += hrow[k + 1] * wi[k + 1];
                    a2 += hrow[k + 2] * wi[k + 2]; a3 += hrow[k + 3] * wi[k + 3];
                }
                sm->xw[tt & 15][lane] = (a0 + a1) + (a2 + a3);
            }
            BARS(2, 64);
            if ((t & 3) == 3) BARS(1, 96);
        }
    } else if (wid == 3) {               // loader warp
        float fg[2][2];
        int avail = 0;
        while (avail < 14) avail = ld_acq(upcnt);
        for (int r = 0; r < 12; r++) {
            const float* src = hin + (size_t)r * HL;
            sm->hin[r][lane] = src[lane];
            if (lane < 16) sm->hin[r][32 + lane] = src[32 + lane];
        }
        {
            const float* s12 = hin + (size_t)12 * HL;
            const float* s13 = hin + (size_t)13 * HL;
            fg[0][0] = s12[lane]; fg[0][1] = (lane < 16) ? s12[32 + lane] : 0.f;
            fg[1][0] = s13[lane]; fg[1][1] = (lane < 16) ? s13[32 + lane] : 0.f;
        }
        __syncthreads();
        for (int t = 0; t < S_LEN; t++) {
            int r_sts = t + 12;
            if (r_sts < S_LEN) {
                float* dst = sm->hin[r_sts & 15];
                dst[lane] = fg[t & 1][0];
                if (lane < 16) dst[32 + lane] = fg[t & 1][1];
            }
            int r_ldg = t + 14;
            if (r_ldg < S_LEN) {
                if (avail <= r_ldg) { do { avail = ld_acq(upcnt); } while (avail <= r_ldg); }
                const float* src = hin + (size_t)r_ldg * HL;
                fg[t & 1][0] = src[lane];
                if (lane < 16) fg[t & 1][1] = src[32 + lane];
            }
            if ((t & 3) == 3) {
                BARS(1, 96);
                if (lane == 0) st_rel(mycnt, t + 1);
            }
        }
    } else {                             // warp 2 idle
        __syncthreads();
    }
}

// ---------------- RNN1 + relu + fc4 -> out ----------------
__device__ void rnn1_stage(unsigned char* smem_raw,
                           const float* __restrict__ Wih, const float* __restrict__ Whh,
                           const float* __restrict__ bih, const float* __restrict__ bhh,
                           const float* __restrict__ rin, const int* upcnt,
                           const float* __restrict__ fc4W, const float* __restrict__ fc4b,
                           float* __restrict__ out)
{
    Rnn1Smem* sm = reinterpret_cast<Rnn1Smem*>(smem_raw);
    const int tid = threadIdx.x;
    const int wid = tid >> 5, lane = tid & 31;
    for (int i = tid; i < 24 * 24; i += 128) sm->W[i] = Wih[i];
    if (tid < 24) { sm->b[tid] = bih[tid] + bhh[tid]; sm->hb[0][tid] = 0.f; }

    if (wid == 0) {                      // recurrence + fc4
        float wh[24], wf[24], bf = 0.f;
        if (lane < 24) {
#pragma unroll
            for (int k = 0; k < 24; k++) wh[k] = Whh[lane * HR + k];
        }
        if (lane == 24 || lane == 25) {
#pragma unroll
            for (int k = 0; k < 24; k++) wf[k] = fc4W[(lane - 24) * HR + k];
            bf = fc4b[lane - 24];
        }
        __syncthreads();
        BARS(2, 64);
        for (int t = 0; t < S_LEN; t++) {
            if (lane < 24) {
                const float* hp = sm->hb[t & 1];
                float a0 = sm->xw[t & 15][lane], a1 = 0, a2 = 0, a3 = 0;
#pragma unroll
                for (int k = 0; k < 24; k += 4) {
                    a0 += hp[k] * wh[k];         a1 += hp[k + 1] * wh[k + 1];
                    a2 += hp[k + 2] * wh[k + 2]; a3 += hp[k + 3] * wh[k + 3];
                }
                float h = tanhap((a0 + a1) + (a2 + a3));
                sm->hb[(t + 1) & 1][lane] = h;
            }
            __syncwarp();
            if (lane == 24 || lane == 25) {
                const float* hc = sm->hb[(t + 1) & 1];
                float a0 = bf, a1 = 0, a2 = 0, a3 = 0;
#pragma unroll
                for (int k = 0; k < 24; k += 4) {
                    a0 += fmaxf(hc[k], 0.f) * wf[k];
                    a1 += fmaxf(hc[k + 1], 0.f) * wf[k + 1];
                    a2 += fmaxf(hc[k + 2], 0.f) * wf[k + 2];
                    a3 += fmaxf(hc[k + 3], 0.f) * wf[k + 3];
                }
                out[(size_t)t * 2 + (lane - 24)] = (a0 + a1) + (a2 + a3);
            }
            BARS(2, 64);
            if ((t & 3) == 3) BARS(1, 96);
        }
    } else if (wid == 1) {               // input projection one step ahead
        float wi[24], bsum = 0.f;
        if (lane < 24) {
#pragma unroll
            for (int k = 0; k < 24; k++) wi[k] = Wih[lane * HR + k];
            bsum = bih[lane] + bhh[lane];
        }
        __syncthreads();
        if (lane < 24) {
            const float* hrow = sm->rin[0];
            float a0 = bsum, a1 = 0, a2 = 0, a3 = 0;
#pragma unroll
            for (int k = 0; k < 24; k += 4) {
                a0 += hrow[k] * wi[k];         a1 += hrow[k + 1] * wi[k + 1];
                a2 += hrow[k + 2] * wi[k + 2]; a3 += hrow[k + 3] * wi[k + 3];
            }
            sm->xw[0][lane] = (a0 + a1) + (a2 + a3);
        }
        BARS(2, 64);
        for (int t = 0; t < S_LEN; t++) {
            int tt = t + 1;
            if (tt < S_LEN && lane < 24) {
                const float* hrow = sm->rin[tt & 15];
                float a0 = bsum, a1 = 0, a2 = 0, a3 = 0;
#pragma unroll
                for (int k = 0; k < 24; k += 4) {
                    a0 += hrow[k] * wi[k];         a1 += hrow[k + 1] * wi[k + 1];
                    a2 += hrow[k + 2] * wi[k + 2]; a3 += hrow[k + 3] * wi[k + 3];
                }
                sm->xw[tt & 15][lane] = (a0 + a1) + (a2 + a3);
            }
            BARS(2, 64);
            if ((t & 3) == 3) BARS(1, 96);
        }
    } else if (wid == 3) {               // loader
        float fg[2];
        int avail = 0;
        while (avail < 14) avail = ld_acq(upcnt);
        for (int r = 0; r < 12; r++) {
            if (lane < 24) sm->rin[r][lane] = rin[(size_t)r * HR + lane];
        }
        fg[0] = (lane < 24) ? rin[(size_t)12 * HR + lane] : 0.f;
        fg[1] = (lane < 24) ? rin[(size_t)13 * HR + lane] : 0.f;
        __syncthreads();
        for (int t = 0; t < S_LEN; t++) {
            int r_sts = t + 12;
            if (r_sts < S_LEN && lane < 24) sm->rin[r_sts & 15][lane] = fg[t & 1];
            int r_ldg = t + 14;
            if (r_ldg < S_LEN) {
                if (avail <= r_ldg) { do { avail = ld_acq(upcnt); } while (avail <= r_ldg); }
                if (lane < 24) fg[t & 1] = rin[(size_t)r_ldg * HR + lane];
            }
            if ((t & 3) == 3) BARS(1, 96);
        }
    } else {
        __syncthreads();
    }
}

// ---------------- pipeline dispatcher ----------------
__global__ void __launch_bounds__(128, 1) pipe_kernel(
    const float* lstm0_Whh,
    const float* lstmr_Wih, const float* lstmr_Whh,
    const float* lstmr_bih, const float* lstmr_bhh,
    const float* rnn0_Wih, const float* rnn0_Whh,
    const float* rnn0_bih, const float* rnn0_bhh,
    const float* rnn1_Wih, const float* rnn1_Whh,
    const float* rnn1_bih, const float* rnn1_bhh,
    const float* fc4W, const float* fc4b,
    float* out)
{
    __shared__ __align__(16) unsigned char smem[SMEM_MAX];
    const int b = blockIdx.x;
    if (b == 0) {
        lstm_rec(smem, lstm0_Whh, g_xw0, 0, g_hb[0], &g_cnt[0]);
    } else if (b <= 8) {
        int l = (b - 1) / 2;
        if ((b & 1) == 1) {
            xw_stage(smem,
                     lstmr_Wih + (size_t)l * 192 * HL,
                     lstmr_bih + (size_t)l * 192,
                     lstmr_bhh + (size_t)l * 192,
                     g_hb[l], &g_cnt[2 * l], g_xwb[l], &g_cnt[2 * l + 1]);
        } else {
            lstm_rec(smem,
                     lstmr_Whh + (size_t)l * 192 * HL,
                     g_xwb[l], &g_cnt[2 * l + 1], g_hb[l + 1], &g_cnt[2 * l + 2]);
        }
    } else if (b == 9) {
        rnn0_stage(smem, rnn0_Wih, rnn0_Whh, rnn0_bih, rnn0_bhh,
                   g_hb[4], &g_cnt[8], g_r0, &g_cnt[9]);
    } else {
        rnn1_stage(smem, rnn1_Wih, rnn1_Whh, rnn1_bih, rnn1_bhh,
                   g_r0, &g_cnt[9], fc4W, fc4b, out);
    }
}

extern "C" void kernel_launch(void* const* d_in, const int* in_sizes, int n_in,
                              void* d_out, int out_size) {
    const float* x         = (const float*)d_in[0];
    const float* fc1_W     = (const float*)d_in[1];
    const float* fc1_b     = (const float*)d_in[2];
    const float* fc2_W     = (const float*)d_in[3];
    const float* fc2_b     = (const float*)d_in[4];
    const float* lstm0_Wih = (const float*)d_in[5];
    const float* lstm0_Whh = (const float*)d_in[6];
    const float* lstm0_bih = (const float*)d_in[7];
    const float* lstm0_bhh = (const float*)d_in[8];
    const float* lstmr_Wih = (const float*)d_in[9];
    const float* lstmr_Whh = (const float*)d_in[10];
    const float* lstmr_bih = (const float*)d_in[11];
    const float* lstmr_bhh = (const float*)d_in[12];
    const float* rnn0_Wih  = (const float*)d_in[13];
    const float* rnn0_Whh  = (const float*)d_in[14];
    const float* rnn0_bih  = (const float*)d_in[15];
    const float* rnn0_bhh  = (const float*)d_in[16];
    const float* rnn1_Wih  = (const float*)d_in[17];
    const float* rnn1_Whh  = (const float*)d_in[18];
    const float* rnn1_bih  = (const float*)d_in[19];
    const float* rnn1_bhh  = (const float*)d_in[20];
    const float* fc4_W     = (const float*)d_in[21];
    const float* fc4_b     = (const float*)d_in[22];
    float* out = (float*)d_out;

    front_kernel<<<S_LEN / 128, 128>>>(x, fc1_W, fc1_b, fc2_W, fc2_b,
                                       lstm0_Wih, lstm0_bih, lstm0_bhh);
    pipe_kernel<<<11, 128>>>(lstm0_Whh,
                             lstmr_Wih, lstmr_Whh, lstmr_bih, lstmr_bhh,
                             rnn0_Wih, rnn0_Whh, rnn0_bih, rnn0_bhh,
                             rnn1_Wih, rnn1_Whh, rnn1_bih, rnn1_bhh,
                             fc4_W, fc4_b, out);
}